// round 2
// baseline (speedup 1.0000x reference)
#include <cuda_runtime.h>
#include <cstdint>

// ReadoutLayer: out[b,d] = sum_n h[b,n,d] * (op_idx[b,n] != 5)
// B=4096, N=64, D=256, fp32 embeddings.
// op_idx: JAX default x64-disabled -> materialized as INT32 (round-1 lesson:
// reading it as int64 gave rel_err 0.385).
//
// One CTA per graph. 256 threads = 4 row-chunks x 64 float4 lanes.
// Pure HBM stream: ~260 MB total traffic, predicted ~45-60 us.

#define SKIP_OP 5

__global__ __launch_bounds__(256, 8)
void readout_kernel(const float4* __restrict__ h,   // [B, 64, 64] as float4
                    const int* __restrict__ op,     // [B, 64] int32
                    float4* __restrict__ out)       // [B, 64] as float4
{
    __shared__ float smask[64];
    __shared__ float4 spart[256];

    const int b   = blockIdx.x;
    const int tid = threadIdx.x;

    // Load the 64 node masks once per CTA (0.0 / 1.0).
    if (tid < 64) {
        smask[tid] = (op[(size_t)b * 64 + tid] != SKIP_OP) ? 1.0f : 0.0f;
    }
    __syncthreads();

    const int v  = tid & 63;        // float4 column within D (64 float4 = 256 floats)
    const int r0 = (tid >> 6) * 16; // first row of this thread's 16-row chunk

    // Row stride in float4 units: 256 floats / 4 = 64.
    const float4* base = h + (size_t)b * 64 * 64 + v;

    float4 acc = make_float4(0.f, 0.f, 0.f, 0.f);

#pragma unroll
    for (int i = 0; i < 16; ++i) {
        const int row = r0 + i;
        const float  m = smask[row];
        const float4 x = base[(size_t)row * 64];
        acc.x = fmaf(m, x.x, acc.x);
        acc.y = fmaf(m, x.y, acc.y);
        acc.z = fmaf(m, x.z, acc.z);
        acc.w = fmaf(m, x.w, acc.w);
    }

    spart[tid] = acc;
    __syncthreads();

    if (tid < 64) {
        const float4 a = spart[tid];
        const float4 c = spart[tid + 64];
        const float4 d = spart[tid + 128];
        const float4 e = spart[tid + 192];
        float4 r;
        r.x = (a.x + c.x) + (d.x + e.x);
        r.y = (a.y + c.y) + (d.y + e.y);
        r.z = (a.z + c.z) + (d.z + e.z);
        r.w = (a.w + c.w) + (d.w + e.w);
        out[(size_t)b * 64 + tid] = r;
    }
}

extern "C" void kernel_launch(void* const* d_in, const int* in_sizes, int n_in,
                              void* d_out, int out_size)
{
    const float4* h  = (const float4*)d_in[0];  // node_embeddings [4096,64,256] f32
    const int*    op = (const int*)d_in[1];     // op_idx [4096,64] int32
    float4*       o  = (float4*)d_out;          // [4096,256] f32

    const int B = in_sizes[1] / 64;             // op_idx has B*64 elements -> B=4096
    readout_kernel<<<B, 256>>>(h, op, o);
}